// round 10
// baseline (speedup 1.0000x reference)
#include <cuda_runtime.h>

// Problem constants
#define TT    1024   // seq len
#define BB    1024   // batch
#define HH    64     // encoder hidden
#define NB    7      // batch elements per CTA
#define CTAS  147    // 147*7 = 1029 >= 1024
#define TSWAP 512    // subgroup load-balancing swap point

// ---------------------------------------------------------------------------
// helpers
// ---------------------------------------------------------------------------
__device__ __forceinline__ void ffma2(unsigned long long &d,
                                      unsigned long long a,
                                      unsigned long long b) {
    asm("fma.rn.f32x2 %0, %1, %2, %0;" : "+l"(d) : "l"(a), "l"(b));
}
__device__ __forceinline__ unsigned long long packf2(float lo, float hi) {
    unsigned long long r;
    asm("mov.b64 %0, {%1,%2};" : "=l"(r) : "f"(lo), "f"(hi));
    return r;
}
__device__ __forceinline__ float ex2f(float x) {
    float r; asm("ex2.approx.f32 %0, %1;" : "=f"(r) : "f"(x)); return r;
}
__device__ __forceinline__ float rcpf(float x) {
    float r; asm("rcp.approx.f32 %0, %1;" : "=f"(r) : "f"(x)); return r;
}

#define L2E      1.4426950408889634f
#define TWO_L2E  2.8853900817779268f

__device__ __forceinline__ float tanhx(float x) {      // rel err ~1e-7
    return fmaf(-2.0f, rcpf(1.0f + ex2f(TWO_L2E * x)), 1.0f);
}

// ---------------------------------------------------------------------------
// Fused encoder+decoder. 147 CTAs x 256 threads (2 warps/SMSP).
// == the R4 best kernel + ONE change: a load-balancing batch swap at t=512 ==
//
// Two independent 128-thread subgroups per CTA, each with its own named
// barrier, so their matvec/epilogue phases drift & interleave on each SMSP.
// Batch sets {0..3} <-> {4..6} are exchanged at t=512 (c handed off via
// SMEM, one full __syncthreads; h needs no handoff -- it lives in the
// shared double buffer, whose parity is continuous across the swap).
// Each subgroup thus does 512*4 + 512*3 step-batches: perfectly balanced,
// so no subgroup ever finishes early and leaves its partner warp running
// solo on the SMSP. Bit-exact vs the unswapped kernel.
//
// Per-thread math (identical to R4):
//   j = (tid&127)>>1, half = tid&1
//   half0 -> gate rows (i,f) = (j, j+64); half1 -> (g,o) = (j+128, j+192)
// 2 gate rows of Whh in regs (64 packed f32x2), activation arg scale folded
// into weights/bias. Phase-split: all nb matvecs into live packed
// accumulators, then all epilogues. Butterfly shfl (lane^1) exchanges
// (i,f)<->(g,o); both halves update c; only half0 computes tanh(c)+store.
// hs double-buffered; x prefetched one step ahead via uniform __ldg.
// Decoder (hidden=1) fused at the end after a full __syncthreads.
// ---------------------------------------------------------------------------
__global__ void __launch_bounds__(256, 1) fused_kernel(
    const float* __restrict__ x,      // [T, B, 1]
    const float* __restrict__ Wih,    // [256, 1]
    const float* __restrict__ Whh,    // [256, 64]
    const float* __restrict__ bih,    // [256]
    const float* __restrict__ bhh,    // [256]
    const float* __restrict__ Wih_d,  // [4, 64]
    const float* __restrict__ Whh_d,  // [4, 1]
    const float* __restrict__ bih_d,  // [4]
    const float* __restrict__ bhh_d,  // [4]
    float* __restrict__ out)          // [T, B, 1]
{
    const int tid  = threadIdx.x;
    const int sub  = tid >> 7;            // 0 or 1
    const int j    = (tid & 127) >> 1;    // 0..63
    const int half = tid & 1;
    const int r0   = half * 128 + j;      // i (half0) / g (half1)
    const int r1   = r0 + 64;             // f (half0) / o (half1)
    const int b0   = blockIdx.x * NB;

    __shared__ __align__(16) float hs[2][NB][HH];  // double-buffered hidden
    __shared__ float cs[NB][HH];                   // c handoff buffer

    // activation parametrization (r0: sigmoid/tanh, r1: sigmoid)
    const float s0 = half ? TWO_L2E : -L2E;
    const float s1 = -L2E;
    const float A0 = half ? -2.0f : 1.0f;
    const float B0 = half ?  1.0f : 0.0f;

    // weights for my two gate rows, pre-scaled, packed over k
    unsigned long long w0[32], w1[32];
    {
        const float2* p0 = (const float2*)(Whh + r0 * HH);
        const float2* p1 = (const float2*)(Whh + r1 * HH);
        #pragma unroll
        for (int i = 0; i < 32; i++) {
            float2 v0 = p0[i], v1 = p1[i];
            w0[i] = packf2(v0.x * s0, v0.y * s0);
            w1[i] = packf2(v1.x * s1, v1.y * s1);
        }
    }
    const float be0  = s0 * (bih[r0] + bhh[r0]);
    const float be1  = s1 * (bih[r1] + bhh[r1]);
    const float wih0 = s0 * Wih[r0];
    const float wih1 = s1 * Wih[r1];

    // current batch assignment (flips at TSWAP)
    int nb     = sub ? 3 : 4;
    int b_base = sub ? 4 : 0;

    int off[4];
    #pragma unroll
    for (int bi = 0; bi < 4; bi++) {
        int gb = b0 + b_base + bi; if (gb > BB - 1) gb = BB - 1;
        off[bi] = gb;
    }
    float xv[4];
    #pragma unroll
    for (int bi = 0; bi < 4; bi++) if (bi < nb) xv[bi] = __ldg(x + off[bi]);

    // init h = 0 (buffer 0)
    for (int i = tid; i < NB * HH; i += 256) ((float*)hs[0])[i] = 0.0f;
    float cc[4] = {0.0f, 0.0f, 0.0f, 0.0f};
    __syncthreads();

    const float* xt = x + BB;   // next step's x row

    for (int t = 0; t < TT; t++) {
        // ---- load-balancing swap (uniform branch, executes once) ----
        if (t == TSWAP) {
            // hand off c through SMEM (half0 lanes of each (j, batch))
            if (!half) {
                #pragma unroll
                for (int bi = 0; bi < 4; bi++)
                    if (bi < nb) cs[b_base + bi][j] = cc[bi];
            }
            __syncthreads();   // also publishes partner's h writes (hs)
            // flip assignment, reload c / x offsets for the new batches
            nb     = sub ? 4 : 3;
            b_base = sub ? 0 : 4;
            #pragma unroll
            for (int bi = 0; bi < 4; bi++) {
                int gb = b0 + b_base + bi; if (gb > BB - 1) gb = BB - 1;
                off[bi] = gb;
            }
            if (!half) {
                #pragma unroll
                for (int bi = 0; bi < 4; bi++)
                    if (bi < nb) cc[bi] = cs[b_base + bi][j];
            }
            #pragma unroll
            for (int bi = 0; bi < 4; bi++)
                if (bi < nb) xv[bi] = __ldg(x + t * BB + off[bi]);
        }

        const float* __restrict__ hr = hs[t & 1][0];
        float* __restrict__       hw = hs[(t + 1) & 1][0];

        // accumulator init: bias + input term (this step's x)
        unsigned long long a0[4], a1[4];
        #pragma unroll
        for (int bi = 0; bi < 4; bi++) if (bi < nb) {
            a0[bi] = packf2(fmaf(wih0, xv[bi], be0), 0.0f);
            a1[bi] = packf2(fmaf(wih1, xv[bi], be1), 0.0f);
        }

        // prefetch next x under the matvec
        if (t + 1 < TT) {
            #pragma unroll
            for (int bi = 0; bi < 4; bi++)
                if (bi < nb) xv[bi] = __ldg(xt + off[bi]);
        }

        // ---- matvec phase: all batches, dense FFMA2 ----
        #pragma unroll
        for (int kk = 0; kk < 16; kk++) {
            #pragma unroll
            for (int bi = 0; bi < 4; bi++) if (bi < nb) {
                ulonglong2 h4 =
                    ((const ulonglong2*)(hr + (b_base + bi) * HH))[kk];
                ffma2(a0[bi], w0[2 * kk],     h4.x);
                ffma2(a0[bi], w0[2 * kk + 1], h4.y);
                ffma2(a1[bi], w1[2 * kk],     h4.x);
                ffma2(a1[bi], w1[2 * kk + 1], h4.y);
            }
        }

        // ---- epilogue phase: activations (independent MUFU chains) ----
        float act0[4], act1[4];
        #pragma unroll
        for (int bi = 0; bi < 4; bi++) if (bi < nb) {
            float l0, h0, l1, h1;
            asm("mov.b64 {%0,%1}, %2;" : "=f"(l0), "=f"(h0) : "l"(a0[bi]));
            asm("mov.b64 {%0,%1}, %2;" : "=f"(l1), "=f"(h1) : "l"(a1[bi]));
            act0[bi] = fmaf(A0, rcpf(1.0f + ex2f(l0 + h0)), B0);
            act1[bi] = rcpf(1.0f + ex2f(l1 + h1));
        }

        // ---- butterfly exchange with partner lane (other gate pair) ----
        float p0[4], p1[4];
        #pragma unroll
        for (int bi = 0; bi < 4; bi++) if (bi < nb) {
            p0[bi] = __shfl_xor_sync(0xffffffffu, act0[bi], 1);
            p1[bi] = __shfl_xor_sync(0xffffffffu, act1[bi], 1);
        }

        // ---- c/h update (only half0 needs tanh(c) + store) ----
        #pragma unroll
        for (int bi = 0; bi < 4; bi++) if (bi < nb) {
            float ai = half ? p0[bi]   : act0[bi];
            float af = half ? p1[bi]   : act1[bi];
            float ag = half ? act0[bi] : p0[bi];
            float ao = half ? act1[bi] : p1[bi];
            cc[bi] = fmaf(af, cc[bi], ai * ag);
            if (!half) {
                float hn = ao * tanhx(cc[bi]);
                hw[(b_base + bi) * HH + j] = hn;
            }
        }

        // per-subgroup barrier: hs slices are subgroup-private
        asm volatile("bar.sync %0, %1;" :: "r"(sub + 1), "r"(128) : "memory");
        xt += BB;
    }
    // final h in hs[0] (t=1023 wrote buffer (1024)&1 = 0)
    __syncthreads();   // decoder reads all batches

    // ------------------- fused decoder (7 threads per CTA) -------------------
    if (tid < NB) {
        const int gb = b0 + tid;
        if (gb < BB) {
            const float* he = hs[0][tid];
            float z[4], wd[4];
            #pragma unroll
            for (int g = 0; g < 4; g++) {
                float acc = bih_d[g] + bhh_d[g];
                const float* wr = Wih_d + g * HH;
                #pragma unroll 8
                for (int k = 0; k < HH; k++) acc = fmaf(wr[k], he[k], acc);
                const float s = (g == 2) ? TWO_L2E : -L2E;
                z[g]  = s * acc;
                wd[g] = s * Whh_d[g];
            }
            float h = 0.0f, c = 0.0f;
            float* op = out + gb;
            for (int t = 0; t < TT; t++) {
                float gi = fmaf(wd[0], h, z[0]);
                float gf = fmaf(wd[1], h, z[1]);
                float gg = fmaf(wd[2], h, z[2]);
                float go = fmaf(wd[3], h, z[3]);
                float ai = rcpf(1.0f + ex2f(gi));
                float af = rcpf(1.0f + ex2f(gf));
                float ag = fmaf(-2.0f, rcpf(1.0f + ex2f(gg)), 1.0f);
                float ao = rcpf(1.0f + ex2f(go));
                c = fmaf(af, c, ai * ag);
                h = ao * tanhx(c);
                *op = h;
                op += BB;
            }
        }
    }
}

// ---------------------------------------------------------------------------
// launch
// ---------------------------------------------------------------------------
extern "C" void kernel_launch(void* const* d_in, const int* in_sizes, int n_in,
                              void* d_out, int out_size) {
    const float* x     = (const float*)d_in[0];
    const float* Wih_e = (const float*)d_in[1];
    const float* Whh_e = (const float*)d_in[2];
    const float* bih_e = (const float*)d_in[3];
    const float* bhh_e = (const float*)d_in[4];
    const float* Wih_d = (const float*)d_in[5];
    const float* Whh_d = (const float*)d_in[6];
    const float* bih_d = (const float*)d_in[7];
    const float* bhh_d = (const float*)d_in[8];
    float* out = (float*)d_out;

    fused_kernel<<<CTAS, 256>>>(x, Wih_e, Whh_e, bih_e, bhh_e,
                                Wih_d, Whh_d, bih_d, bhh_d, out);
}

// round 11
// speedup vs baseline: 1.0591x; 1.0591x over previous
#include <cuda_runtime.h>

// Problem constants
#define TT    1024   // seq len
#define BB    1024   // batch
#define HH    64     // encoder hidden
#define NB    7      // batch elements per CTA
#define CTAS  147    // 147*7 = 1029 >= 1024

// ---------------------------------------------------------------------------
// helpers
// ---------------------------------------------------------------------------
__device__ __forceinline__ void ffma2(unsigned long long &d,
                                      unsigned long long a,
                                      unsigned long long b) {
    asm("fma.rn.f32x2 %0, %1, %2, %0;" : "+l"(d) : "l"(a), "l"(b));
}
__device__ __forceinline__ unsigned long long packf2(float lo, float hi) {
    unsigned long long r;
    asm("mov.b64 %0, {%1,%2};" : "=l"(r) : "f"(lo), "f"(hi));
    return r;
}
__device__ __forceinline__ float ex2f(float x) {
    float r; asm("ex2.approx.f32 %0, %1;" : "=f"(r) : "f"(x)); return r;
}
__device__ __forceinline__ float rcpf(float x) {
    float r; asm("rcp.approx.f32 %0, %1;" : "=f"(r) : "f"(x)); return r;
}

#define L2E      1.4426950408889634f
#define TWO_L2E  2.8853900817779268f

__device__ __forceinline__ float tanhx(float x) {      // rel err ~1e-7
    return fmaf(-2.0f, rcpf(1.0f + ex2f(TWO_L2E * x)), 1.0f);
}

// ---------------------------------------------------------------------------
// Fused encoder+decoder. 147 CTAs x 256 threads (2 warps/SMSP).
// == R4 (the best kernel) with compile-time-specialized subgroup loops and
//    a fused per-batch epilogue. Math is bit-identical to R4. ==
//
// Two independent 128-thread subgroups per CTA own batches {0..3} / {4..6},
// each with its own named barrier, so their matvec/epilogue phases drift and
// interleave on each SMSP. The time loop is instantiated ONCE PER SUBGROUP
// via macro with literal NBV/BBASE/barrier-id: every hs offset and loop
// bound constant-folds (no runtime nb predicates, no computed addressing).
//
// Per-thread math: j = (tid&127)>>1, half = tid&1
//   half0 -> gate rows (i,f) = (j, j+64); half1 -> (g,o) = (j+128, j+192)
// 2 gate rows of Whh in regs (64 packed f32x2), activation arg scale folded
// into weights/bias. Matvec phase-split (all batches dense FFMA2), then a
// FUSED per-batch epilogue: act -> butterfly shfl (lane^1) -> c/h update,
// minimizing live ranges. Only half0 owns c / tanh(c) / h store.
// hs double-buffered; x prefetched one step ahead via uniform __ldg.
// Decoder (hidden=1) fused at the end after a full __syncthreads.
// ---------------------------------------------------------------------------

// One subgroup's full encoder time loop. NBV/BBASE/BARID are literals.
#define ENC_LOOP(NBV, BBASE, BARID)                                           \
do {                                                                          \
    int off[NBV];                                                             \
    _Pragma("unroll")                                                         \
    for (int bi = 0; bi < NBV; bi++) {                                        \
        int gb = b0 + BBASE + bi; if (gb > BB - 1) gb = BB - 1;               \
        off[bi] = gb;                                                         \
    }                                                                         \
    float xv[NBV];                                                            \
    _Pragma("unroll")                                                         \
    for (int bi = 0; bi < NBV; bi++) xv[bi] = __ldg(x + off[bi]);             \
    const float* xt = x + BB;                                                 \
    for (int t = 0; t < TT; t++) {                                            \
        const float* __restrict__ hr = hs[t & 1][0];                          \
        float* __restrict__       hw = hs[(t + 1) & 1][0];                    \
        unsigned long long a0[NBV], a1[NBV];                                  \
        _Pragma("unroll")                                                     \
        for (int bi = 0; bi < NBV; bi++) {                                    \
            a0[bi] = packf2(fmaf(wih0, xv[bi], be0), 0.0f);                   \
            a1[bi] = packf2(fmaf(wih1, xv[bi], be1), 0.0f);                   \
        }                                                                     \
        if (t + 1 < TT) {                                                     \
            _Pragma("unroll")                                                 \
            for (int bi = 0; bi < NBV; bi++) xv[bi] = __ldg(xt + off[bi]);    \
        }                                                                     \
        _Pragma("unroll")                                                     \
        for (int kk = 0; kk < 16; kk++) {                                     \
            _Pragma("unroll")                                                 \
            for (int bi = 0; bi < NBV; bi++) {                                \
                ulonglong2 h4 =                                               \
                    ((const ulonglong2*)(hr + (BBASE + bi) * HH))[kk];        \
                ffma2(a0[bi], w0[2 * kk],     h4.x);                          \
                ffma2(a0[bi], w0[2 * kk + 1], h4.y);                          \
                ffma2(a1[bi], w1[2 * kk],     h4.x);                          \
                ffma2(a1[bi], w1[2 * kk + 1], h4.y);                          \
            }                                                                 \
        }                                                                     \
        _Pragma("unroll")                                                     \
        for (int bi = 0; bi < NBV; bi++) {                                    \
            float l0, h0, l1, h1;                                             \
            asm("mov.b64 {%0,%1}, %2;" : "=f"(l0), "=f"(h0) : "l"(a0[bi]));   \
            asm("mov.b64 {%0,%1}, %2;" : "=f"(l1), "=f"(h1) : "l"(a1[bi]));   \
            float act0 = fmaf(A0, rcpf(1.0f + ex2f(l0 + h0)), B0);            \
            float act1 = rcpf(1.0f + ex2f(l1 + h1));                          \
            float p0 = __shfl_xor_sync(0xffffffffu, act0, 1);                 \
            float p1 = __shfl_xor_sync(0xffffffffu, act1, 1);                 \
            if (!half) {   /* half0: act0=i, act1=f, p0=g~, p1=o */           \
                cc[bi] = fmaf(act1, cc[bi], act0 * p0);                       \
                hw[(BBASE + bi) * HH + j] = p1 * tanhx(cc[bi]);               \
            }                                                                 \
        }                                                                     \
        asm volatile("bar.sync %0, %1;" :: "n"(BARID), "r"(128) : "memory");  \
        xt += BB;                                                             \
    }                                                                         \
} while (0)

__global__ void __launch_bounds__(256, 1) fused_kernel(
    const float* __restrict__ x,      // [T, B, 1]
    const float* __restrict__ Wih,    // [256, 1]
    const float* __restrict__ Whh,    // [256, 64]
    const float* __restrict__ bih,    // [256]
    const float* __restrict__ bhh,    // [256]
    const float* __restrict__ Wih_d,  // [4, 64]
    const float* __restrict__ Whh_d,  // [4, 1]
    const float* __restrict__ bih_d,  // [4]
    const float* __restrict__ bhh_d,  // [4]
    float* __restrict__ out)          // [T, B, 1]
{
    const int tid  = threadIdx.x;
    const int sub  = tid >> 7;            // 0 or 1
    const int j    = (tid & 127) >> 1;    // 0..63
    const int half = tid & 1;
    const int r0   = half * 128 + j;      // i (half0) / g (half1)
    const int r1   = r0 + 64;             // f (half0) / o (half1)
    const int b0   = blockIdx.x * NB;

    __shared__ __align__(16) float hs[2][NB][HH];  // double-buffered hidden

    // activation parametrization (r0: sigmoid/tanh, r1: sigmoid)
    const float s0 = half ? TWO_L2E : -L2E;
    const float s1 = -L2E;
    const float A0 = half ? -2.0f : 1.0f;
    const float B0 = half ?  1.0f : 0.0f;

    // weights for my two gate rows, pre-scaled, packed over k
    unsigned long long w0[32], w1[32];
    {
        const float2* p0 = (const float2*)(Whh + r0 * HH);
        const float2* p1 = (const float2*)(Whh + r1 * HH);
        #pragma unroll
        for (int i = 0; i < 32; i++) {
            float2 v0 = p0[i], v1 = p1[i];
            w0[i] = packf2(v0.x * s0, v0.y * s0);
            w1[i] = packf2(v1.x * s1, v1.y * s1);
        }
    }
    const float be0  = s0 * (bih[r0] + bhh[r0]);
    const float be1  = s1 * (bih[r1] + bhh[r1]);
    const float wih0 = s0 * Wih[r0];
    const float wih1 = s1 * Wih[r1];

    // init h = 0 (buffer 0)
    for (int i = tid; i < NB * HH; i += 256) ((float*)hs[0])[i] = 0.0f;
    float cc[4] = {0.0f, 0.0f, 0.0f, 0.0f};
    __syncthreads();

    // compile-time specialized subgroup loops (uniform branch per subgroup)
    if (sub == 0) {
        ENC_LOOP(4, 0, 1);
    } else {
        ENC_LOOP(3, 4, 2);
    }

    // final h in hs[0] (t=1023 wrote buffer (1024)&1 = 0)
    __syncthreads();   // decoder reads all batches

    // ------------------- fused decoder (7 threads per CTA) -------------------
    if (tid < NB) {
        const int gb = b0 + tid;
        if (gb < BB) {
            const float* he = hs[0][tid];
            float z[4], wd[4];
            #pragma unroll
            for (int g = 0; g < 4; g++) {
                float acc = bih_d[g] + bhh_d[g];
                const float* wr = Wih_d + g * HH;
                #pragma unroll 8
                for (int k = 0; k < HH; k++) acc = fmaf(wr[k], he[k], acc);
                const float s = (g == 2) ? TWO_L2E : -L2E;
                z[g]  = s * acc;
                wd[g] = s * Whh_d[g];
            }
            float h = 0.0f, c = 0.0f;
            float* op = out + gb;
            for (int t = 0; t < TT; t++) {
                float gi = fmaf(wd[0], h, z[0]);
                float gf = fmaf(wd[1], h, z[1]);
                float gg = fmaf(wd[2], h, z[2]);
                float go = fmaf(wd[3], h, z[3]);
                float ai = rcpf(1.0f + ex2f(gi));
                float af = rcpf(1.0f + ex2f(gf));
                float ag = fmaf(-2.0f, rcpf(1.0f + ex2f(gg)), 1.0f);
                float ao = rcpf(1.0f + ex2f(go));
                c = fmaf(af, c, ai * ag);
                h = ao * tanhx(c);
                *op = h;
                op += BB;
            }
        }
    }
}

// ---------------------------------------------------------------------------
// launch
// ---------------------------------------------------------------------------
extern "C" void kernel_launch(void* const* d_in, const int* in_sizes, int n_in,
                              void* d_out, int out_size) {
    const float* x     = (const float*)d_in[0];
    const float* Wih_e = (const float*)d_in[1];
    const float* Whh_e = (const float*)d_in[2];
    const float* bih_e = (const float*)d_in[3];
    const float* bhh_e = (const float*)d_in[4];
    const float* Wih_d = (const float*)d_in[5];
    const float* Whh_d = (const float*)d_in[6];
    const float* bih_d = (const float*)d_in[7];
    const float* bhh_d = (const float*)d_in[8];
    float* out = (float*)d_out;

    fused_kernel<<<CTAS, 256>>>(x, Wih_e, Whh_e, bih_e, bhh_e,
                                Wih_d, Whh_d, bih_d, bhh_d, out);
}